// round 12
// baseline (speedup 1.0000x reference)
#include <cuda_runtime.h>
#include <cuda_bf16.h>

#define NNODES 8192
#define NEDGES 262144
#define NFEAT  128
#define NREP   4
#define CAP    48        // max edges per (row, rep) sub-bucket

// ---------------- device scratch (no allocation allowed) ----------------
__device__ __align__(16) float g_support[NNODES * NFEAT];        // x @ W (4 MB)
__device__ __align__(16) float g_deg4[NNODES * NREP];            // replicated degree
__device__ __align__(16) float g_dinv[NNODES];
__device__ __align__(16) int   g_cnt4[NNODES * NREP];            // bucket cursors
__device__ __align__(16) int2  g_bucket[NNODES * NREP * CAP];    // {col, w} (12.6 MB)

// ---------------- K1: single-pass bucketed scatter + degree ----------------
__global__ void k_scatter(const int* __restrict__ rows,
                          const int* __restrict__ cols,
                          const float* __restrict__ ew) {
    int e = blockIdx.x * blockDim.x + threadIdx.x;
    int r = rows[e];
    float w = ew[e];
    int slot = r * 4 + (e & 3);
    int pos = atomicAdd(&g_cnt4[slot], 1);
    g_bucket[slot * CAP + pos] = make_int2(cols[e], __float_as_int(w));
    atomicAdd(&g_deg4[slot], w);
}

// ---------------- K2: dinv = rsqrt(1 + deg + eps)  (elementwise) ------------
__global__ void k_dinv() {
    int i = blockIdx.x * blockDim.x + threadIdx.x;
    if (i < NNODES) {
        float4 d = *(const float4*)&g_deg4[i * 4];
        g_dinv[i] = rsqrtf(1.0f + d.x + d.y + d.z + d.w + 1e-10f);
    }
}

// ---------------- packed f32x2 helpers ----------------
__device__ __forceinline__ unsigned long long pack2(float lo, float hi) {
    unsigned long long r;
    asm("mov.b64 %0, {%1, %2};" : "=l"(r) : "f"(lo), "f"(hi));
    return r;
}
__device__ __forceinline__ void fma2(unsigned long long& d,
                                     unsigned long long a,
                                     unsigned long long b) {
    asm("fma.rn.f32x2 %0, %1, %2, %0;" : "+l"(d) : "l"(a), "l"(b));
}
__device__ __forceinline__ float2 unpack2(unsigned long long p) {
    float lo, hi;
    asm("mov.b64 {%0, %1}, %2;" : "=f"(lo), "=f"(hi) : "l"(p));
    return make_float2(lo, hi);
}

// ---------------- K3: support = x @ W  (8192x128x128 fp32, f32x2 FMA) -------
__global__ __launch_bounds__(256) void k_gemm(const float* __restrict__ x,
                                              const float* __restrict__ w) {
    __shared__ __align__(16) float s_x[32][32];
    __shared__ __align__(16) float s_w[32][128];
    int tid = threadIdx.x;
    int row_base = blockIdx.x * 32;
    int c0 = (tid & 31) * 4;
    int r0 = (tid >> 5) * 4;

    unsigned long long acc2[4][2];
#pragma unroll
    for (int i = 0; i < 4; i++) { acc2[i][0] = 0ull; acc2[i][1] = 0ull; }

    for (int kk = 0; kk < 128; kk += 32) {
#pragma unroll
        for (int q = 0; q < 4; q++) {
            int e = tid + 256 * q;
            int r = e >> 5, kl = e & 31;
            s_x[r][kl] = x[(row_base + r) * 128 + kk + kl];
        }
#pragma unroll
        for (int q = 0; q < 4; q++) {
            int p = tid + 256 * q;
            int kr = p >> 5, cc = (p & 31) * 4;
            *(float4*)&s_w[kr][cc] = *(const float4*)&w[(kk + kr) * 128 + cc];
        }
        __syncthreads();
#pragma unroll
        for (int k = 0; k < 32; k++) {
            float4 bv = *(float4*)&s_w[k][c0];
            unsigned long long b01 = pack2(bv.x, bv.y);
            unsigned long long b23 = pack2(bv.z, bv.w);
#pragma unroll
            for (int i = 0; i < 4; i++) {
                float av = s_x[r0 + i][k];
                unsigned long long aa = pack2(av, av);
                fma2(acc2[i][0], aa, b01);
                fma2(acc2[i][1], aa, b23);
            }
        }
        __syncthreads();
    }
#pragma unroll
    for (int i = 0; i < 4; i++) {
        float2 lo = unpack2(acc2[i][0]);
        float2 hi = unpack2(acc2[i][1]);
        *(float4*)&g_support[(row_base + r0 + i) * 128 + c0] =
            make_float4(lo.x, lo.y, hi.x, hi.y);
    }
}

// ---------------- K4: SpMM — staged entries + broadcast gather --------------
// Phase 1: 32 lanes resolve {col, v=w*dinv[col]} for 32 edges in parallel.
// Phase 2: broadcast each staged entry; all lanes gather support row, FFMA.
__global__ __launch_bounds__(256) void k_spmm(const float* __restrict__ bias,
                                              float* __restrict__ out) {
    __shared__ __align__(8) int2 s_ent[8][32];     // per-warp staging (2 KB)
    int wib  = threadIdx.x >> 5;
    int lane = threadIdx.x & 31;
    int row  = blockIdx.x * 8 + wib;
    int foff = lane * 4;

    int4 cnt = *(const int4*)&g_cnt4[row * 4];
    int o1 = cnt.x;
    int o2 = o1 + cnt.y;
    int o3 = o2 + cnt.z;
    int nt = o3 + cnt.w;                  // total edges this row

    float ax = 0.f, ay = 0.f, az = 0.f, aw = 0.f;

    for (int base = 0; base < nt; base += 32) {
        int idx = base + lane;
        int2 ent = make_int2(row, 0);     // padding: col=row (L2-hot), v=0
        if (idx < nt) {
            int k, off;
            if (idx < o1)      { k = 0; off = idx; }
            else if (idx < o2) { k = 1; off = idx - o1; }
            else if (idx < o3) { k = 2; off = idx - o2; }
            else               { k = 3; off = idx - o3; }
            int2 e = g_bucket[(row * 4 + k) * CAP + off];
            float v = __int_as_float(e.y) * g_dinv[e.x];
            ent = make_int2(e.x, __float_as_int(v));
        }
        s_ent[wib][lane] = ent;
        __syncwarp();

        int m = nt - base; if (m > 32) m = 32;
        int m4 = (m + 3) & ~3;            // padded entries are harmless (v=0)
        for (int j = 0; j < m4; j += 4) {
            int2 t0 = s_ent[wib][j];
            int2 t1 = s_ent[wib][j + 1];
            int2 t2 = s_ent[wib][j + 2];
            int2 t3 = s_ent[wib][j + 3];
            float4 s0 = *(const float4*)&g_support[t0.x * 128 + foff];
            float4 s1 = *(const float4*)&g_support[t1.x * 128 + foff];
            float4 s2 = *(const float4*)&g_support[t2.x * 128 + foff];
            float4 s3 = *(const float4*)&g_support[t3.x * 128 + foff];
            float v0 = __int_as_float(t0.y);
            float v1 = __int_as_float(t1.y);
            float v2 = __int_as_float(t2.y);
            float v3 = __int_as_float(t3.y);
            ax += v0 * s0.x + v1 * s1.x + v2 * s2.x + v3 * s3.x;
            ay += v0 * s0.y + v1 * s1.y + v2 * s2.y + v3 * s3.y;
            az += v0 * s0.z + v1 * s1.z + v2 * s2.z + v3 * s3.z;
            aw += v0 * s0.w + v1 * s1.w + v2 * s2.w + v3 * s3.w;
        }
        __syncwarp();
    }

    // self-loop: dinv[row]^2 * support[row]
    float di = g_dinv[row];
    float4 sv = *(const float4*)&g_support[row * 128 + foff];
    ax += di * sv.x; ay += di * sv.y; az += di * sv.z; aw += di * sv.w;

    float4 b = *(const float4*)&bias[foff];
    float4 o;
    o.x = di * ax + b.x;
    o.y = di * ay + b.y;
    o.z = di * az + b.z;
    o.w = di * aw + b.w;
    *(float4*)&out[row * 128 + foff] = o;
}

// ---------------- launch ----------------
extern "C" void kernel_launch(void* const* d_in, const int* in_sizes, int n_in,
                              void* d_out, int out_size) {
    const float* x    = (const float*)d_in[0];
    const int*   adj  = (const int*)d_in[1];     // int32 [2, E]
    const float* ew   = (const float*)d_in[2];
    const float* wgt  = (const float*)d_in[3];
    const float* bias = (const float*)d_in[4];
    float* out = (float*)d_out;

    const int* rows = adj;
    const int* cols = adj + NEDGES;

    // one-time side resources (host-side only; no device allocation)
    static cudaStream_t s2 = nullptr;
    static cudaEvent_t evA = nullptr, evB = nullptr;
    if (s2 == nullptr) {
        cudaStreamCreateWithFlags(&s2, cudaStreamNonBlocking);
        cudaEventCreateWithFlags(&evA, cudaEventDisableTiming);
        cudaEventCreateWithFlags(&evB, cudaEventDisableTiming);
    }

    // fork: GEMM (depends only on x, W) runs concurrently with the bucket build
    cudaEventRecord(evA, 0);
    cudaStreamWaitEvent(s2, evA, 0);
    k_gemm<<<NNODES / 32, 256, 0, s2>>>(x, wgt);
    cudaEventRecord(evB, s2);

    // bucket build on the main (capture) stream
    void* cnt_ptr = nullptr; cudaGetSymbolAddress(&cnt_ptr, g_cnt4);
    void* deg_ptr = nullptr; cudaGetSymbolAddress(&deg_ptr, g_deg4);
    cudaMemsetAsync(cnt_ptr, 0, NNODES * NREP * sizeof(int), 0);
    cudaMemsetAsync(deg_ptr, 0, NNODES * NREP * sizeof(float), 0);
    k_scatter<<<NEDGES / 256, 256>>>(rows, cols, ew);
    k_dinv<<<NNODES / 256, 256>>>();

    // join, then SpMM (warp per row)
    cudaStreamWaitEvent(0, evB, 0);
    k_spmm<<<NNODES / 8, 256>>>(bias, out);
}